// round 5
// baseline (speedup 1.0000x reference)
#include <cuda_runtime.h>
#include <cuda.h>
#include <cuda_bf16.h>
#include <cstdint>
#include <cstddef>

// ---------------- problem constants ----------------
#define HID   128
#define GSZ   512            // 4*H gate width
#define BATCH 1024
#define TLEN  512
#define DIN   12

#define KP0   144            // D + H padded to multiple of 4
#define KP1   256            // H + H
#define RES   32             // smem-resident weight rows (both layers)
#define STG_ROWS 32          // rows per staging stage
#define BT    8              // batch rows per block
#define NBLK  (BATCH / BT)   // 128 blocks
#define CLSZ  4              // cluster size (weight multicast group)

typedef unsigned long long ull;

// ---------------- device scratch (no-alloc rule: __device__ globals) ----------------
__device__ float g_W0T[KP0 * GSZ];                 // [k][j] transposed weights, layer 0
__device__ float g_W1T[KP1 * GSZ];                 // [k][j] transposed weights, layer 1
__device__ float g_bias0[GSZ];
__device__ float g_bias1[GSZ];
__device__ float g_h1[(size_t)TLEN * BATCH * HID]; // layer-0 hidden states (T,B,H)
__device__ float g_h2[BATCH * HID];                // layer-1 final hidden state

// ---------------- small helpers ----------------
__device__ __forceinline__ uint32_t smem_u32(const void* p) {
    uint32_t a;
    asm("{ .reg .u64 t; cvta.to.shared.u64 t, %1; cvt.u32.u64 %0, t; }" : "=r"(a) : "l"(p));
    return a;
}
__device__ __forceinline__ uint32_t ctarank() {
    uint32_t r; asm("mov.u32 %0, %%cluster_ctarank;" : "=r"(r)); return r;
}
__device__ __forceinline__ ull dup2(float x) {
    ull d; asm("mov.b64 %0, {%1, %1};" : "=l"(d) : "f"(x)); return d;
}
__device__ __forceinline__ ull fma2(ull a, ull b, ull c) {
    ull d; asm("fma.rn.f32x2 %0, %1, %2, %3;" : "=l"(d) : "l"(a), "l"(b), "l"(c)); return d;
}
__device__ __forceinline__ float2 unp(ull v) {
    float2 r; asm("mov.b64 {%0, %1}, %2;" : "=f"(r.x), "=f"(r.y) : "l"(v)); return r;
}
__device__ __forceinline__ float sigm(float x) {
    return __fdividef(1.0f, 1.0f + __expf(-x));
}
__device__ __forceinline__ float tanh_f(float x) {
    return __fdividef(2.0f, 1.0f + __expf(-2.0f * x)) - 1.0f;
}

// ---------------- mbarrier / TMA / cluster macros ----------------
#define MBARRIER_INIT(addr, cnt) \
    asm volatile("mbarrier.init.shared.b64 [%0], %1;" :: "r"((uint32_t)(addr)), "r"((uint32_t)(cnt)) : "memory")

#define MBARRIER_EXPECT_TX(addr, bytes) \
    asm volatile("mbarrier.arrive.expect_tx.shared.b64 _, [%0], %1;" :: "r"((uint32_t)(addr)), "r"((uint32_t)(bytes)) : "memory")

#define MBARRIER_ARRIVE_CLUSTER(addr, rank)                              \
    asm volatile(                                                        \
        "{\n\t.reg .b32 ra;\n\t"                                         \
        "mapa.shared::cluster.u32 ra, %0, %1;\n\t"                       \
        "mbarrier.arrive.shared::cluster.b64 _, [ra];\n\t}"              \
        :: "r"((uint32_t)(addr)), "r"((uint32_t)(rank)) : "memory")

#define MBARRIER_WAIT_PARITY(addr, par) do {                                         \
    asm volatile(                                                                    \
        "{\n\t.reg .pred P1;\n\t"                                                    \
        "WL_%=:\n\t"                                                                 \
        "mbarrier.try_wait.parity.acquire.cta.shared::cta.b64 P1, [%0], %1, 0x989680;\n\t" \
        "@P1 bra.uni WD_%=;\n\t"                                                     \
        "bra.uni WL_%=;\n\t"                                                         \
        "WD_%=:\n\t}"                                                                \
        :: "r"((uint32_t)(addr)), "r"((uint32_t)(par)) : "memory");                  \
} while (0)

#define MBARRIER_WAIT_PARITY_RELAXED(addr, par) do {                                 \
    asm volatile(                                                                    \
        "{\n\t.reg .pred P1;\n\t"                                                    \
        "WL_%=:\n\t"                                                                 \
        "mbarrier.try_wait.parity.relaxed.cta.shared::cta.b64 P1, [%0], %1, 0x989680;\n\t" \
        "@P1 bra.uni WD_%=;\n\t"                                                     \
        "bra.uni WL_%=;\n\t"                                                         \
        "WD_%=:\n\t}"                                                                \
        :: "r"((uint32_t)(addr)), "r"((uint32_t)(par)) : "memory");                  \
} while (0)

// 1-D TMA load, multicast across cluster
#define TMA_1D_MC(dst, map, xe, mbar, mask)                                          \
    asm volatile(                                                                    \
        "cp.async.bulk.tensor.1d.shared::cluster.global.tile.mbarrier::complete_tx::bytes.multicast::cluster " \
        "[%0], [%1, {%2}], [%3], %4;"                                                \
        :: "r"((uint32_t)(dst)), "l"(map), "r"((int32_t)(xe)),                       \
           "r"((uint32_t)(mbar)), "h"((uint16_t)(mask)) : "memory")

#define CLUSTER_SYNC() do {                                         \
    asm volatile("barrier.cluster.arrive.aligned;" ::: "memory");   \
    asm volatile("barrier.cluster.wait.aligned;" ::: "memory");     \
} while (0)

// one weight row's contribution to all 8 accumulators
#define FMA_ROW(W2V, KIDX)                                                    \
    do {                                                                      \
        ull w0 = dup2((W2V).x), w1 = dup2((W2V).y);                           \
        ulonglong2 vA = *(const ulonglong2*)&v_s[(KIDX) * 12];                \
        ulonglong2 vB = *(const ulonglong2*)&v_s[(KIDX) * 12 + 4];            \
        a0 = fma2(w0, vA.x, a0); a1 = fma2(w0, vA.y, a1);                     \
        a2 = fma2(w0, vB.x, a2); a3 = fma2(w0, vB.y, a3);                     \
        a4 = fma2(w1, vA.x, a4); a5 = fma2(w1, vA.y, a5);                     \
        a6 = fma2(w1, vB.x, a6); a7 = fma2(w1, vB.y, a7);                     \
    } while (0)

// ---------------- prep: transpose/concat weights + fold biases ----------------
__global__ void prep_kernel(const float* __restrict__ Wih0, const float* __restrict__ Whh0,
                            const float* __restrict__ bih0, const float* __restrict__ bhh0,
                            const float* __restrict__ Wih1, const float* __restrict__ Whh1,
                            const float* __restrict__ bih1, const float* __restrict__ bhh1) {
    int i = blockIdx.x * blockDim.x + threadIdx.x;
    if (i < KP0 * GSZ) {
        int k = i / GSZ, j = i % GSZ;
        float v = 0.0f;
        if (k < DIN)            v = Wih0[j * DIN + k];
        else if (k < DIN + HID) v = Whh0[j * HID + (k - DIN)];
        g_W0T[i] = v;                          // pad rows stay zero
    } else if (i < (KP0 + KP1) * GSZ) {
        int i2 = i - KP0 * GSZ;
        int k = i2 / GSZ, j = i2 % GSZ;
        g_W1T[i2] = (k < HID) ? Wih1[j * HID + k] : Whh1[j * HID + (k - HID)];
    } else if (i < (KP0 + KP1) * GSZ + GSZ) {
        int j = i - (KP0 + KP1) * GSZ;
        g_bias0[j] = bih0[j] + bhh0[j];
    } else if (i < (KP0 + KP1) * GSZ + 2 * GSZ) {
        int j = i - (KP0 + KP1) * GSZ - GSZ;
        g_bias1[j] = bih1[j] + bhh1[j];
    }
}

// issue one weight chunk (this CTA's quarter-slice, multicast to all 4 CTAs)
template <int KP, int NCH>
__device__ __forceinline__ void issue_chunk(const CUtensorMap* tm, int g, int rank,
                                            uint32_t sbase, uint32_t fb0, uint32_t fb1) {
    int c    = g % NCH;
    int r0   = RES + 32 * c;
    int rows = (KP - r0 < 32) ? (KP - r0) : 32;
    int st   = g & 1;
    uint32_t fb = st ? fb1 : fb0;
    MBARRIER_EXPECT_TX(fb, (uint32_t)(rows * GSZ * 4));
    int nper = rows >> 2;                              // rows per CTA slice
    uint32_t dstbase = sbase + (uint32_t)((RES * GSZ + st * STG_ROWS * GSZ) * 4);
    int rg0 = r0 + rank * nper;
    for (int i = 0; i < nper; i++) {
        int xe = (rg0 + i) * GSZ;
        uint32_t d = dstbase + (uint32_t)((rank * nper + i) * GSZ * 4);
        TMA_1D_MC(d,        tm, xe,       fb, 0xF);
        TMA_1D_MC(d + 1024, tm, xe + 256, fb, 0xF);
    }
}

// ---------------- fused LSTM layer ----------------
// One block = 8 batch rows, persistent over all T steps. Clusters of 4 CTAs
// share the streamed weight rows via TMA multicast (2-stage smem ring).
template <int LAYER>
__global__ void __launch_bounds__(256, 1) __cluster_dims__(CLSZ, 1, 1)
lstm_kernel(const __grid_constant__ CUtensorMap tmap, const float* __restrict__ x) {
    constexpr int KP    = (LAYER == 0) ? KP0 : KP1;
    constexpr int KOFF  = (LAYER == 0) ? DIN : HID;
    constexpr int NCH   = (KP - RES + 31) / 32;        // L0: 4, L1: 7
    constexpr int TOTAL = TLEN * NCH;
    const float* __restrict__ WT   = (LAYER == 0) ? g_W0T : g_W1T;
    const float* __restrict__ bias = (LAYER == 0) ? g_bias0 : g_bias1;

    extern __shared__ float smem[];
    float* w_res = smem;                               // RES * 512
    float* w_stg = w_res + RES * GSZ;                  // 2 * 32 * 512
    float* v_s   = w_stg + 2 * STG_ROWS * GSZ;         // KP * 12
    float* g_s   = v_s + KP * 12;                      // 8 * 512
    const uint32_t sbase  = smem_u32(smem);
    const uint32_t barOff = (uint32_t)((RES * GSZ + 2 * STG_ROWS * GSZ + KP * 12 + 8 * GSZ) * 4);
    const uint32_t fb0 = sbase + barOff,      fb1 = sbase + barOff + 8;
    const uint32_t eb0 = sbase + barOff + 16, eb1 = sbase + barOff + 24;

    const int tid  = threadIdx.x;
    const int wid  = tid >> 5;
    const int lane = tid & 31;
    const int b0   = blockIdx.x * BT;
    const int j0   = 2 * tid;
    const int rank = (int)ctarank();

    // resident rows -> smem (once)
    {
        const float2* wsrc = (const float2*)WT;
        float2*       wdst = (float2*)w_res;
        for (int i = tid; i < RES * GSZ / 2; i += 256) wdst[i] = wsrc[i];
    }
    for (int i = tid; i < KP * 12; i += 256) v_s[i] = 0.0f;   // h0 = 0

    if (tid == 0) {
        MBARRIER_INIT(fb0, 1);
        MBARRIER_INIT(fb1, 1);
        MBARRIER_INIT(eb0, 32);   // 8 warps x 4 CTAs
        MBARRIER_INIT(eb1, 32);
    }
    __syncthreads();
    CLUSTER_SYNC();               // barriers visible cluster-wide before multicast

    // pre-issue chunks 0 and 1 (stages fresh -> no empty wait)
    if (wid < 2 && lane == 0)
        issue_chunk<KP, NCH>(&tmap, wid, rank, sbase, fb0, fb1);

    const float2 bj = *(const float2*)&bias[j0];
    const ull bxd = dup2(bj.x);
    const ull byd = dup2(bj.y);

    const int ub = tid >> 5;      // update phase: batch row
    const int um = tid & 31;      // update phase: base hidden index
    float c_r[4] = {0.f, 0.f, 0.f, 0.f};

    int gg = 0;                   // global chunk counter
    for (int t = 0; t < TLEN; t++) {
        // ---- stage this step's inputs (x or h1) into registers ----
        float xstage = 0.0f;
        float2 hstA, hstB;
        int st_r = 0, st_c2 = 0;
        if (LAYER == 0) {
            if (tid < 96) {
                int bl = tid / 12, d = tid % 12;
                st_r = bl; st_c2 = d;
                xstage = x[(((size_t)(b0 + bl)) * TLEN + t) * DIN + d];
            }
        } else {
            st_r  = tid >> 5;
            st_c2 = (tid & 31) * 2;
            const float* hrow = &g_h1[(((size_t)t) * BATCH + b0 + st_r) * HID];
            hstA = *(const float2*)&hrow[st_c2];
            hstB = *(const float2*)&hrow[st_c2 + 64];
        }

        // ---- apply previous step's gates: update (h, c) ----
        if (t > 0) {
#pragma unroll
            for (int q = 0; q < 4; q++) {
                int m = um + 32 * q;
                float iv = sigm(g_s[ub * GSZ + m]);
                float fv = sigm(g_s[ub * GSZ + 128 + m]);
                float gv = tanh_f(g_s[ub * GSZ + 256 + m]);
                float ov = sigm(g_s[ub * GSZ + 384 + m]);
                float c  = fv * c_r[q] + iv * gv;
                c_r[q]   = c;
                float h  = ov * tanh_f(c);
                v_s[(KOFF + m) * 12 + ub] = h;
                if (LAYER == 0)
                    g_h1[(((size_t)(t - 1)) * BATCH + b0 + ub) * HID + m] = h;
            }
        }

        // ---- commit staged inputs to v_s ----
        if (LAYER == 0) {
            if (tid < 96) v_s[st_c2 * 12 + st_r] = xstage;
        } else {
            v_s[(st_c2 + 0)  * 12 + st_r] = hstA.x;
            v_s[(st_c2 + 1)  * 12 + st_r] = hstA.y;
            v_s[(st_c2 + 64) * 12 + st_r] = hstB.x;
            v_s[(st_c2 + 65) * 12 + st_r] = hstB.y;
        }
        __syncthreads();

        // ---- gate GEMV ----
        ull a0 = bxd, a1 = bxd, a2 = bxd, a3 = bxd;
        ull a4 = byd, a5 = byd, a6 = byd, a7 = byd;

        // resident rows
#pragma unroll 4
        for (int k = 0; k < RES; k++) {
            float2 w = *(const float2*)&w_res[k * GSZ + j0];
            FMA_ROW(w, k);
        }

        // streamed chunks through the 2-stage multicast ring
        for (int c = 0; c < NCH; c++, gg++) {
            int st   = gg & 1;
            int cpar = (gg >> 1) & 1;
            uint32_t fb = st ? fb1 : fb0;
            uint32_t eb = st ? eb1 : eb0;
            MBARRIER_WAIT_PARITY(fb, cpar);

            int r0   = RES + 32 * c;
            int rows = (KP - r0 < 32) ? (KP - r0) : 32;
            const float* ws = w_stg + st * STG_ROWS * GSZ;
#pragma unroll 4
            for (int i = 0; i < rows; i++) {
                float2 w = *(const float2*)&ws[i * GSZ + j0];
                FMA_ROW(w, r0 + i);
            }

            // release this stage to all 4 CTAs
            if (lane == 0) {
                MBARRIER_ARRIVE_CLUSTER(eb, 0);
                MBARRIER_ARRIVE_CLUSTER(eb, 1);
                MBARRIER_ARRIVE_CLUSTER(eb, 2);
                MBARRIER_ARRIVE_CLUSTER(eb, 3);
            }

            // produce chunk gg+2 (its stage was just released by gg)
            int g2 = gg + 2;
            if (g2 < TOTAL && wid == (g2 % NCH) && lane == 0) {
                int st2  = g2 & 1;
                int ppar = (((g2 >> 1) & 1)) ^ 1;
                MBARRIER_WAIT_PARITY_RELAXED(st2 ? eb1 : eb0, ppar);
                issue_chunk<KP, NCH>(&tmap, g2, rank, sbase, fb0, fb1);
            }
        }

        // ---- write gates to g_s[b][j] ----
        {
            ull ac0[4] = {a0, a1, a2, a3};
            ull ac1[4] = {a4, a5, a6, a7};
#pragma unroll
            for (int p = 0; p < 4; p++) {
                float2 u0 = unp(ac0[p]);
                float2 u1 = unp(ac1[p]);
                *(float2*)&g_s[(2 * p) * GSZ + j0]     = make_float2(u0.x, u1.x);
                *(float2*)&g_s[(2 * p + 1) * GSZ + j0] = make_float2(u0.y, u1.y);
            }
        }
        __syncthreads();
    }

    // ---- final update for t = T-1 ----
#pragma unroll
    for (int q = 0; q < 4; q++) {
        int m = um + 32 * q;
        float iv = sigm(g_s[ub * GSZ + m]);
        float fv = sigm(g_s[ub * GSZ + 128 + m]);
        float gv = tanh_f(g_s[ub * GSZ + 256 + m]);
        float ov = sigm(g_s[ub * GSZ + 384 + m]);
        float c  = fv * c_r[q] + iv * gv;
        float h  = ov * tanh_f(c);
        if (LAYER == 0)
            g_h1[(((size_t)(TLEN - 1)) * BATCH + b0 + ub) * HID + m] = h;
        else
            g_h2[(b0 + ub) * HID + m] = h;
    }

    CLUSTER_SYNC();   // no CTA exits while peers' mbarrier traffic may be in flight
}

// ---------------- MLP head: relu(128->64) -> relu(64->32) -> 32->2 ----------------
__global__ void head_kernel(const float* __restrict__ W1, const float* __restrict__ b1,
                            const float* __restrict__ W2, const float* __restrict__ b2,
                            const float* __restrict__ W3, const float* __restrict__ b3,
                            float* __restrict__ out) {
    __shared__ float hrow[HID];
    __shared__ float z1[64];
    __shared__ float z2[32];
    int b   = blockIdx.x;
    int tid = threadIdx.x;  // 64 threads

    hrow[tid]      = g_h2[b * HID + tid];
    hrow[tid + 64] = g_h2[b * HID + tid + 64];
    __syncthreads();
    {
        float s = b1[tid];
        const float* w = &W1[tid * HID];
#pragma unroll 8
        for (int k = 0; k < HID; k++) s += w[k] * hrow[k];
        z1[tid] = fmaxf(s, 0.0f);
    }
    __syncthreads();
    if (tid < 32) {
        float s = b2[tid];
        const float* w = &W2[tid * 64];
#pragma unroll 8
        for (int k = 0; k < 64; k++) s += w[k] * z1[k];
        z2[tid] = fmaxf(s, 0.0f);
    }
    __syncthreads();
    if (tid < 2) {
        float s = b3[tid];
        const float* w = &W3[tid * 32];
#pragma unroll
        for (int k = 0; k < 32; k++) s += w[k] * z2[k];
        out[b * 2 + tid] = s;
    }
}

// ---------------- host: tensormap construction (no -lcuda link dependency) ----------
typedef CUresult (*EncodeTiledFn)(
    CUtensorMap*, CUtensorMapDataType, cuuint32_t, void*,
    const cuuint64_t*, const cuuint64_t*, const cuuint32_t*, const cuuint32_t*,
    CUtensorMapInterleave, CUtensorMapSwizzle, CUtensorMapL2promotion,
    CUtensorMapFloatOOBfill);

static bool build_tmap(CUtensorMap* tm, void* base, unsigned long long nelem) {
    static EncodeTiledFn fn = nullptr;
    if (!fn) {
        cudaDriverEntryPointQueryResult qr;
        void* p = nullptr;
        cudaGetDriverEntryPointByVersion("cuTensorMapEncodeTiled", &p, 12000,
                                         cudaEnableDefault, &qr);
        fn = (EncodeTiledFn)p;
    }
    if (!fn) return false;
    cuuint64_t dims[1]    = {nelem};
    cuuint64_t strides[1] = {nelem * 4};   // unused for rank 1
    cuuint32_t box[1]     = {256};
    cuuint32_t es[1]      = {1};
    CUresult r = fn(tm, CU_TENSOR_MAP_DATA_TYPE_FLOAT32, 1, base,
                    dims, strides, box, es,
                    CU_TENSOR_MAP_INTERLEAVE_NONE, CU_TENSOR_MAP_SWIZZLE_NONE,
                    CU_TENSOR_MAP_L2_PROMOTION_NONE, CU_TENSOR_MAP_FLOAT_OOB_FILL_NONE);
    return r == CUDA_SUCCESS;
}

// ---------------- launch ----------------
extern "C" void kernel_launch(void* const* d_in, const int* in_sizes, int n_in,
                              void* d_out, int out_size) {
    const float* x    = (const float*)d_in[0];
    const float* Wih0 = (const float*)d_in[1];
    const float* Whh0 = (const float*)d_in[2];
    const float* bih0 = (const float*)d_in[3];
    const float* bhh0 = (const float*)d_in[4];
    const float* Wih1 = (const float*)d_in[5];
    const float* Whh1 = (const float*)d_in[6];
    const float* bih1 = (const float*)d_in[7];
    const float* bhh1 = (const float*)d_in[8];
    const float* W1   = (const float*)d_in[9];
    const float* b1   = (const float*)d_in[10];
    const float* W2   = (const float*)d_in[11];
    const float* b2   = (const float*)d_in[12];
    const float* W3   = (const float*)d_in[13];
    const float* b3   = (const float*)d_in[14];
    float* out = (float*)d_out;

    static CUtensorMap tm0, tm1;
    void *p0 = nullptr, *p1 = nullptr;
    cudaGetSymbolAddress(&p0, g_W0T);
    cudaGetSymbolAddress(&p1, g_W1T);
    build_tmap(&tm0, p0, (unsigned long long)KP0 * GSZ);
    build_tmap(&tm1, p1, (unsigned long long)KP1 * GSZ);

    const int smem0 = (RES * GSZ + 2 * STG_ROWS * GSZ + KP0 * 12 + 8 * GSZ) * 4 + 64;
    const int smem1 = (RES * GSZ + 2 * STG_ROWS * GSZ + KP1 * 12 + 8 * GSZ) * 4 + 64;
    cudaFuncSetAttribute((const void*)lstm_kernel<0>,
                         cudaFuncAttributeMaxDynamicSharedMemorySize, smem0);
    cudaFuncSetAttribute((const void*)lstm_kernel<1>,
                         cudaFuncAttributeMaxDynamicSharedMemorySize, smem1);

    int tot = (KP0 + KP1) * GSZ + 2 * GSZ;
    prep_kernel<<<(tot + 255) / 256, 256>>>(Wih0, Whh0, bih0, bhh0,
                                            Wih1, Whh1, bih1, bhh1);
    lstm_kernel<0><<<NBLK, 256, smem0>>>(tm0, x);
    lstm_kernel<1><<<NBLK, 256, smem1>>>(tm1, nullptr);
    head_kernel<<<BATCH, 64>>>(W1, b1, W2, b2, W3, b3, out);
}

// round 6
// speedup vs baseline: 1.3790x; 1.3790x over previous
#include <cuda_runtime.h>
#include <cuda_bf16.h>
#include <cstdint>
#include <cstddef>

// ---------------- problem constants ----------------
#define HID   128
#define GSZ   512            // 4*H gate width
#define BATCH 1024
#define TLEN  512
#define DIN   12

#define KP0   144            // D + H padded to even (pad rows zero)
#define KP1   256            // H + H
#define SRR   96             // smem-resident weight rows (both layers) = 48 k-pairs
#define RES2  48             // resident k-pairs
#define BT    8              // batch rows per block
#define NBLK  (BATCH / BT)   // 128 blocks
#define NTHR  512

typedef unsigned long long ull;

// Weight layout (prepped): interleaved k-pairs, [k2][j][e] with e in {0,1},
// element (k2,j,e) = W[2*k2+e][j].  One LDS/LDG.64 yields (W[2k2][j], W[2k2+1][j]).
__device__ float g_W0T[KP0 * GSZ];
__device__ float g_W1T[KP1 * GSZ];
__device__ float g_bias0[GSZ];
__device__ float g_bias1[GSZ];
__device__ float g_h1[(size_t)TLEN * BATCH * HID]; // layer-0 hidden states (T,B,H)
__device__ float g_h2[BATCH * HID];                // layer-1 final hidden state

// ---------------- helpers ----------------
__device__ __forceinline__ ull fma2(ull a, ull b, ull c) {
    ull d; asm("fma.rn.f32x2 %0, %1, %2, %3;" : "=l"(d) : "l"(a), "l"(b), "l"(c)); return d;
}
__device__ __forceinline__ float2 unp(ull v) {
    float2 r; asm("mov.b64 {%0, %1}, %2;" : "=f"(r.x), "=f"(r.y) : "l"(v)); return r;
}
__device__ __forceinline__ float sigm(float x) {
    return __fdividef(1.0f, 1.0f + __expf(-x));
}
__device__ __forceinline__ float tanh_f(float x) {
    return __fdividef(2.0f, 1.0f + __expf(-2.0f * x)) - 1.0f;
}

// v_s layout: per k-pair p, 20-float row (16 used): v_s[p*20 + 2*b + e] = val[2p+e][b].
// One k-pair's contribution of all 8 batch rows to the split-K accumulators.
#define FMA_PAIR(W2, P)                                                       \
    do {                                                                      \
        ulonglong2 vA = *(const ulonglong2*)&v_s[(P) * 20];                   \
        ulonglong2 vB = *(const ulonglong2*)&v_s[(P) * 20 + 4];               \
        ulonglong2 vC = *(const ulonglong2*)&v_s[(P) * 20 + 8];               \
        ulonglong2 vD = *(const ulonglong2*)&v_s[(P) * 20 + 12];              \
        ac0 = fma2(W2, vA.x, ac0); ac1 = fma2(W2, vA.y, ac1);                 \
        ac2 = fma2(W2, vB.x, ac2); ac3 = fma2(W2, vB.y, ac3);                 \
        ac4 = fma2(W2, vC.x, ac4); ac5 = fma2(W2, vC.y, ac5);                 \
        ac6 = fma2(W2, vD.x, ac6); ac7 = fma2(W2, vD.y, ac7);                 \
    } while (0)

// ---------------- prep: interleave weights into k-pair layout + fold biases --------
__global__ void prep_kernel(const float* __restrict__ Wih0, const float* __restrict__ Whh0,
                            const float* __restrict__ bih0, const float* __restrict__ bhh0,
                            const float* __restrict__ Wih1, const float* __restrict__ Whh1,
                            const float* __restrict__ bih1, const float* __restrict__ bhh1) {
    int i = blockIdx.x * blockDim.x + threadIdx.x;
    if (i < KP0 * GSZ) {
        int e = i & 1, j = (i >> 1) & (GSZ - 1), k2 = i >> 10;
        int k = 2 * k2 + e;
        float v = 0.0f;
        if (k < DIN)            v = Wih0[j * DIN + k];
        else if (k < DIN + HID) v = Whh0[j * HID + (k - DIN)];
        g_W0T[i] = v;
    } else if (i < (KP0 + KP1) * GSZ) {
        int i2 = i - KP0 * GSZ;
        int e = i2 & 1, j = (i2 >> 1) & (GSZ - 1), k2 = i2 >> 10;
        int k = 2 * k2 + e;
        g_W1T[i2] = (k < HID) ? Wih1[j * HID + k] : Whh1[j * HID + (k - HID)];
    } else if (i < (KP0 + KP1) * GSZ + GSZ) {
        int j = i - (KP0 + KP1) * GSZ;
        g_bias0[j] = bih0[j] + bhh0[j];
    } else if (i < (KP0 + KP1) * GSZ + 2 * GSZ) {
        int j = i - (KP0 + KP1) * GSZ - GSZ;
        g_bias1[j] = bih1[j] + bhh1[j];
    }
}

// ---------------- fused LSTM layer ----------------
// One block = 8 batch rows, 512 threads, persistent over all T steps.
// Thread t owns gate column j = t; accumulators acc[b] are f32x2 split-K
// partials (even-k, odd-k) per batch row b. Weight k-pairs: [0,RES2) smem,
// [RES2,SB2) registers, [SB2,K2) streamed (L1 only) via rolling ring.
template <int LAYER>
__global__ void __launch_bounds__(NTHR, 1)
lstm_kernel(const float* __restrict__ x) {
    constexpr int KP   = (LAYER == 0) ? KP0 : KP1;
    constexpr int K2   = KP / 2;
    constexpr int KOFF = (LAYER == 0) ? DIN : HID;
    constexpr int PB2  = (LAYER == 0) ? 24 : 16;   // register-resident k-pairs
    constexpr int SB2  = RES2 + PB2;               // stream base (k-pairs)
    constexpr int NGRP = (K2 - SB2) / 4;           // stream groups of 4 pairs (L0:0, L1:16)
    const float* __restrict__ WT   = (LAYER == 0) ? g_W0T : g_W1T;
    const float* __restrict__ bias = (LAYER == 0) ? g_bias0 : g_bias1;

    extern __shared__ float smem[];
    float* w_s = smem;                   // RES2 * 512 * 2 floats
    float* v_s = w_s + RES2 * GSZ * 2;   // K2 * 20 floats
    float* g_s = v_s + K2 * 20;          // 8 * 512 gates [b][j]

    const int tid = threadIdx.x;
    const int b0  = blockIdx.x * BT;
    const int j   = tid;

    // resident k-pairs -> smem (once)
    {
        const float4* src = (const float4*)WT;
        float4*       dst = (float4*)w_s;
        for (int i = tid; i < RES2 * GSZ * 2 / 4; i += NTHR) dst[i] = src[i];
    }
    for (int i = tid; i < K2 * 20; i += NTHR) v_s[i] = 0.0f;   // h0 = 0, pads = 0

    // register-resident k-pairs (step-invariant)
    ull pbuf[PB2];
#pragma unroll
    for (int i = 0; i < PB2; i++)
        pbuf[i] = *(const ull*)&WT[((RES2 + i) * GSZ + j) * 2];

    const float bj = bias[j];

    const int ub = tid >> 6;      // update: batch row (0..7)
    const int um = tid & 63;      // update: base hidden index
    float c_r[2] = {0.f, 0.f};

    ull rbuf[4][4];               // rolling stream ring (L1)

    for (int t = 0; t < TLEN; t++) {
        // ---- pre-issue first 3 stream groups (covered by update phase) ----
        if (NGRP > 0) {
#pragma unroll
            for (int gp = 0; gp < 3; gp++)
#pragma unroll
                for (int i = 0; i < 4; i++)
                    rbuf[gp][i] = *(const ull*)&WT[((SB2 + gp * 4 + i) * GSZ + j) * 2];
        }

        // ---- stage this step's inputs (x or h1) into registers ----
        float xstage = 0.0f;
        float2 hst;
        int st_r = 0, st_d = 0, st_c2 = 0;
        if (LAYER == 0) {
            if (tid < 96) {
                st_r = tid / 12; st_d = tid % 12;
                xstage = x[(((size_t)(b0 + st_r)) * TLEN + t) * DIN + st_d];
            }
        } else {
            st_r  = tid >> 6;
            st_c2 = (tid & 63) * 2;
            hst = *(const float2*)&g_h1[(((size_t)t) * BATCH + b0 + st_r) * HID + st_c2];
        }

        // ---- apply previous step's gates: update (h, c) ----
        if (t > 0) {
#pragma unroll
            for (int q = 0; q < 2; q++) {
                int m = um + 64 * q;
                float iv = sigm(g_s[ub * GSZ + m]);
                float fv = sigm(g_s[ub * GSZ + 128 + m]);
                float gv = tanh_f(g_s[ub * GSZ + 256 + m]);
                float ov = sigm(g_s[ub * GSZ + 384 + m]);
                float c  = fv * c_r[q] + iv * gv;
                c_r[q]   = c;
                float h  = ov * tanh_f(c);
                int kk   = KOFF + m;
                v_s[(kk >> 1) * 20 + 2 * ub + (kk & 1)] = h;
                if (LAYER == 0)
                    g_h1[(((size_t)(t - 1)) * BATCH + b0 + ub) * HID + m] = h;
            }
        }

        // ---- commit staged inputs to v_s ----
        if (LAYER == 0) {
            if (tid < 96) v_s[(st_d >> 1) * 20 + 2 * st_r + (st_d & 1)] = xstage;
        } else {
            *(float2*)&v_s[(st_c2 >> 1) * 20 + 2 * st_r] = hst;  // (even-k, odd-k) pair
        }
        __syncthreads();

        // ---- gate GEMV: acc[b] = f32x2 split-K partials ----
        ull ac0 = 0, ac1 = 0, ac2 = 0, ac3 = 0, ac4 = 0, ac5 = 0, ac6 = 0, ac7 = 0;

        // 1) smem-resident k-pairs
#pragma unroll 2
        for (int p = 0; p < RES2; p++) {
            ull w2 = *(const ull*)&w_s[(p * GSZ + j) * 2];
            FMA_PAIR(w2, p);
        }

        // 2) register-resident k-pairs
#pragma unroll
        for (int i = 0; i < PB2; i++)
            FMA_PAIR(pbuf[i], RES2 + i);

        // 3) streamed k-pairs (L1): rolling ring, depth-3
        if (NGRP > 0) {
#pragma unroll 4
            for (int g = 0; g < NGRP; g++) {
                int slot = g & 3;
                int pb   = SB2 + g * 4;
#pragma unroll
                for (int i = 0; i < 4; i++)
                    FMA_PAIR(rbuf[slot][i], pb + i);
                int gp = g + 3;
                if (gp < NGRP) {
#pragma unroll
                    for (int i = 0; i < 4; i++)
                        rbuf[gp & 3][i] = *(const ull*)&WT[((SB2 + gp * 4 + i) * GSZ + j) * 2];
                }
            }
        }

        // ---- finalize gates: fold split-K + bias, write g_s[b][j] ----
        {
            ull acs[8] = {ac0, ac1, ac2, ac3, ac4, ac5, ac6, ac7};
#pragma unroll
            for (int b = 0; b < 8; b++) {
                float2 u = unp(acs[b]);
                g_s[b * GSZ + j] = u.x + u.y + bj;
            }
        }
        __syncthreads();
    }

    // ---- final update for t = T-1 ----
#pragma unroll
    for (int q = 0; q < 2; q++) {
        int m = um + 64 * q;
        float iv = sigm(g_s[ub * GSZ + m]);
        float fv = sigm(g_s[ub * GSZ + 128 + m]);
        float gv = tanh_f(g_s[ub * GSZ + 256 + m]);
        float ov = sigm(g_s[ub * GSZ + 384 + m]);
        float c  = fv * c_r[q] + iv * gv;
        float h  = ov * tanh_f(c);
        if (LAYER == 0)
            g_h1[(((size_t)(TLEN - 1)) * BATCH + b0 + ub) * HID + m] = h;
        else
            g_h2[(b0 + ub) * HID + m] = h;
    }
}

// ---------------- MLP head: relu(128->64) -> relu(64->32) -> 32->2 ----------------
__global__ void head_kernel(const float* __restrict__ W1, const float* __restrict__ b1,
                            const float* __restrict__ W2, const float* __restrict__ b2,
                            const float* __restrict__ W3, const float* __restrict__ b3,
                            float* __restrict__ out) {
    __shared__ float hrow[HID];
    __shared__ float z1[64];
    __shared__ float z2[32];
    int b   = blockIdx.x;
    int tid = threadIdx.x;  // 64 threads

    hrow[tid]      = g_h2[b * HID + tid];
    hrow[tid + 64] = g_h2[b * HID + tid + 64];
    __syncthreads();
    {
        float s = b1[tid];
        const float* w = &W1[tid * HID];
#pragma unroll 8
        for (int k = 0; k < HID; k++) s += w[k] * hrow[k];
        z1[tid] = fmaxf(s, 0.0f);
    }
    __syncthreads();
    if (tid < 32) {
        float s = b2[tid];
        const float* w = &W2[tid * 64];
#pragma unroll 8
        for (int k = 0; k < 64; k++) s += w[k] * z1[k];
        z2[tid] = fmaxf(s, 0.0f);
    }
    __syncthreads();
    if (tid < 2) {
        float s = b3[tid];
        const float* w = &W3[tid * 32];
#pragma unroll
        for (int k = 0; k < 32; k++) s += w[k] * z2[k];
        out[b * 2 + tid] = s;
    }
}

// ---------------- launch ----------------
extern "C" void kernel_launch(void* const* d_in, const int* in_sizes, int n_in,
                              void* d_out, int out_size) {
    const float* x    = (const float*)d_in[0];
    const float* Wih0 = (const float*)d_in[1];
    const float* Whh0 = (const float*)d_in[2];
    const float* bih0 = (const float*)d_in[3];
    const float* bhh0 = (const float*)d_in[4];
    const float* Wih1 = (const float*)d_in[5];
    const float* Whh1 = (const float*)d_in[6];
    const float* bih1 = (const float*)d_in[7];
    const float* bhh1 = (const float*)d_in[8];
    const float* W1   = (const float*)d_in[9];
    const float* b1   = (const float*)d_in[10];
    const float* W2   = (const float*)d_in[11];
    const float* b2   = (const float*)d_in[12];
    const float* W3   = (const float*)d_in[13];
    const float* b3   = (const float*)d_in[14];
    float* out = (float*)d_out;

    const int smem0 = (RES2 * GSZ * 2 + (KP0 / 2) * 20 + 8 * GSZ) * (int)sizeof(float); // 218,752 B
    const int smem1 = (RES2 * GSZ * 2 + (KP1 / 2) * 20 + 8 * GSZ) * (int)sizeof(float); // 223,232 B
    cudaFuncSetAttribute((const void*)lstm_kernel<0>,
                         cudaFuncAttributeMaxDynamicSharedMemorySize, smem0);
    cudaFuncSetAttribute((const void*)lstm_kernel<1>,
                         cudaFuncAttributeMaxDynamicSharedMemorySize, smem1);

    int tot = (KP0 + KP1) * GSZ + 2 * GSZ;
    prep_kernel<<<(tot + 255) / 256, 256>>>(Wih0, Whh0, bih0, bhh0,
                                            Wih1, Whh1, bih1, bhh1);
    lstm_kernel<0><<<NBLK, NTHR, smem0>>>(x);
    lstm_kernel<1><<<NBLK, NTHR, smem1>>>(nullptr);
    head_kernel<<<BATCH, 64>>>(W1, b1, W2, b2, W3, b3, out);
}

// round 7
// speedup vs baseline: 1.3807x; 1.0012x over previous
#include <cuda_runtime.h>
#include <cuda_bf16.h>
#include <cstdint>
#include <cstddef>

// ---------------- problem constants ----------------
#define HID   128
#define GSZ   512            // 4*H gate width
#define BATCH 1024
#define TLEN  512
#define DIN   12

#define KP0   144            // D + H padded to even (pad rows zero)
#define KP1   256            // H + H
#define SRR   96             // smem-resident weight rows (both layers) = 48 k-pairs
#define RES2  48             // resident k-pairs
#define BT    8              // batch rows per block
#define NBLK  (BATCH / BT)   // 128 blocks
#define NTHR  512

typedef unsigned long long ull;

// Weight layout (prepped): interleaved k-pairs, [k2][j][e] with e in {0,1},
// element (k2,j,e) = W[2*k2+e][j].  One LDS/LDG.64 yields (W[2k2][j], W[2k2+1][j]).
__device__ float g_W0T[KP0 * GSZ];
__device__ float g_W1T[KP1 * GSZ];
__device__ float g_bias0[GSZ];
__device__ float g_bias1[GSZ];
__device__ float g_h1[(size_t)TLEN * BATCH * HID]; // layer-0 hidden states (T,B,H)
__device__ float g_h2[BATCH * HID];                // layer-1 final hidden state

// ---------------- helpers ----------------
__device__ __forceinline__ ull fma2(ull a, ull b, ull c) {
    ull d; asm("fma.rn.f32x2 %0, %1, %2, %3;" : "=l"(d) : "l"(a), "l"(b), "l"(c)); return d;
}
__device__ __forceinline__ float2 unp(ull v) {
    float2 r; asm("mov.b64 {%0, %1}, %2;" : "=f"(r.x), "=f"(r.y) : "l"(v)); return r;
}
__device__ __forceinline__ float sigm(float x) {
    return __fdividef(1.0f, 1.0f + __expf(-x));
}
__device__ __forceinline__ float tanh_f(float x) {
    return __fdividef(2.0f, 1.0f + __expf(-2.0f * x)) - 1.0f;
}

// v_s layout: per k-pair p, 20-float row (16 used): v_s[p*20 + 2*b + e] = val[2p+e][b].
// One k-pair's contribution of all 8 batch rows to the split-K accumulators.
#define FMA_PAIR(W2, P)                                                       \
    do {                                                                      \
        ulonglong2 vA = *(const ulonglong2*)&v_s[(P) * 20];                   \
        ulonglong2 vB = *(const ulonglong2*)&v_s[(P) * 20 + 4];               \
        ulonglong2 vC = *(const ulonglong2*)&v_s[(P) * 20 + 8];               \
        ulonglong2 vD = *(const ulonglong2*)&v_s[(P) * 20 + 12];              \
        ac0 = fma2(W2, vA.x, ac0); ac1 = fma2(W2, vA.y, ac1);                 \
        ac2 = fma2(W2, vB.x, ac2); ac3 = fma2(W2, vB.y, ac3);                 \
        ac4 = fma2(W2, vC.x, ac4); ac5 = fma2(W2, vC.y, ac5);                 \
        ac6 = fma2(W2, vD.x, ac6); ac7 = fma2(W2, vD.y, ac7);                 \
    } while (0)

// ---------------- prep: interleave weights into k-pair layout + fold biases --------
__global__ void prep_kernel(const float* __restrict__ Wih0, const float* __restrict__ Whh0,
                            const float* __restrict__ bih0, const float* __restrict__ bhh0,
                            const float* __restrict__ Wih1, const float* __restrict__ Whh1,
                            const float* __restrict__ bih1, const float* __restrict__ bhh1) {
    int i = blockIdx.x * blockDim.x + threadIdx.x;
    if (i < KP0 * GSZ) {
        int e = i & 1, j = (i >> 1) & (GSZ - 1), k2 = i >> 10;
        int k = 2 * k2 + e;
        float v = 0.0f;
        if (k < DIN)            v = Wih0[j * DIN + k];
        else if (k < DIN + HID) v = Whh0[j * HID + (k - DIN)];
        g_W0T[i] = v;
    } else if (i < (KP0 + KP1) * GSZ) {
        int i2 = i - KP0 * GSZ;
        int e = i2 & 1, j = (i2 >> 1) & (GSZ - 1), k2 = i2 >> 10;
        int k = 2 * k2 + e;
        g_W1T[i2] = (k < HID) ? Wih1[j * HID + k] : Whh1[j * HID + (k - HID)];
    } else if (i < (KP0 + KP1) * GSZ + GSZ) {
        int j = i - (KP0 + KP1) * GSZ;
        g_bias0[j] = bih0[j] + bhh0[j];
    } else if (i < (KP0 + KP1) * GSZ + 2 * GSZ) {
        int j = i - (KP0 + KP1) * GSZ - GSZ;
        g_bias1[j] = bih1[j] + bhh1[j];
    }
}

// ---------------- fused LSTM layer ----------------
// One block = 8 batch rows, 512 threads, persistent over all T steps.
// Thread t owns gate column j = t; accumulators acc[b] are f32x2 split-K
// partials (even-k, odd-k) per batch row b. Weight k-pairs: [0,RES2) smem,
// [RES2,SB2) registers, [SB2,K2) streamed (L1 only) via rolling ring.
template <int LAYER>
__global__ void __launch_bounds__(NTHR, 1)
lstm_kernel(const float* __restrict__ x) {
    constexpr int KP   = (LAYER == 0) ? KP0 : KP1;
    constexpr int K2   = KP / 2;
    constexpr int KOFF = (LAYER == 0) ? DIN : HID;
    constexpr int PB2  = (LAYER == 0) ? 24 : 16;   // register-resident k-pairs
    constexpr int SB2  = RES2 + PB2;               // stream base (k-pairs)
    constexpr int NGRP = (K2 - SB2) / 4;           // stream groups of 4 pairs (L0:0, L1:16)
    const float* __restrict__ WT   = (LAYER == 0) ? g_W0T : g_W1T;
    const float* __restrict__ bias = (LAYER == 0) ? g_bias0 : g_bias1;

    extern __shared__ float smem[];
    float* w_s = smem;                   // RES2 * 512 * 2 floats
    float* v_s = w_s + RES2 * GSZ * 2;   // K2 * 20 floats
    float* g_s = v_s + K2 * 20;          // 8 * 512 gates [b][j]

    const int tid = threadIdx.x;
    const int b0  = blockIdx.x * BT;
    const int j   = tid;

    // resident k-pairs -> smem (once)
    {
        const float4* src = (const float4*)WT;
        float4*       dst = (float4*)w_s;
        for (int i = tid; i < RES2 * GSZ * 2 / 4; i += NTHR) dst[i] = src[i];
    }
    for (int i = tid; i < K2 * 20; i += NTHR) v_s[i] = 0.0f;   // h0 = 0, pads = 0

    // register-resident k-pairs (step-invariant)
    ull pbuf[PB2];
#pragma unroll
    for (int i = 0; i < PB2; i++)
        pbuf[i] = *(const ull*)&WT[((RES2 + i) * GSZ + j) * 2];

    const float bj = bias[j];

    const int ub = tid >> 6;      // update: batch row (0..7)
    const int um = tid & 63;      // update: base hidden index
    float c_r[2] = {0.f, 0.f};

    ull rbuf[4][4];               // rolling stream ring (L1)

    for (int t = 0; t < TLEN; t++) {
        // ---- pre-issue first 3 stream groups (covered by update phase) ----
        if (NGRP > 0) {
#pragma unroll
            for (int gp = 0; gp < 3; gp++)
#pragma unroll
                for (int i = 0; i < 4; i++)
                    rbuf[gp][i] = *(const ull*)&WT[((SB2 + gp * 4 + i) * GSZ + j) * 2];
        }

        // ---- stage this step's inputs (x or h1) into registers ----
        float xstage = 0.0f;
        float2 hst;
        int st_r = 0, st_d = 0, st_c2 = 0;
        if (LAYER == 0) {
            if (tid < 96) {
                st_r = tid / 12; st_d = tid % 12;
                xstage = x[(((size_t)(b0 + st_r)) * TLEN + t) * DIN + st_d];
            }
        } else {
            st_r  = tid >> 6;
            st_c2 = (tid & 63) * 2;
            hst = *(const float2*)&g_h1[(((size_t)t) * BATCH + b0 + st_r) * HID + st_c2];
        }

        // ---- apply previous step's gates: update (h, c) ----
        if (t > 0) {
#pragma unroll
            for (int q = 0; q < 2; q++) {
                int m = um + 64 * q;
                float iv = sigm(g_s[ub * GSZ + m]);
                float fv = sigm(g_s[ub * GSZ + 128 + m]);
                float gv = tanh_f(g_s[ub * GSZ + 256 + m]);
                float ov = sigm(g_s[ub * GSZ + 384 + m]);
                float c  = fv * c_r[q] + iv * gv;
                c_r[q]   = c;
                float h  = ov * tanh_f(c);
                int kk   = KOFF + m;
                v_s[(kk >> 1) * 20 + 2 * ub + (kk & 1)] = h;
                if (LAYER == 0)
                    g_h1[(((size_t)(t - 1)) * BATCH + b0 + ub) * HID + m] = h;
            }
        }

        // ---- commit staged inputs to v_s ----
        if (LAYER == 0) {
            if (tid < 96) v_s[(st_d >> 1) * 20 + 2 * st_r + (st_d & 1)] = xstage;
        } else {
            *(float2*)&v_s[(st_c2 >> 1) * 20 + 2 * st_r] = hst;  // (even-k, odd-k) pair
        }
        __syncthreads();

        // ---- gate GEMV: acc[b] = f32x2 split-K partials ----
        ull ac0 = 0, ac1 = 0, ac2 = 0, ac3 = 0, ac4 = 0, ac5 = 0, ac6 = 0, ac7 = 0;

        // 1) smem-resident k-pairs
#pragma unroll 2
        for (int p = 0; p < RES2; p++) {
            ull w2 = *(const ull*)&w_s[(p * GSZ + j) * 2];
            FMA_PAIR(w2, p);
        }

        // 2) register-resident k-pairs
#pragma unroll
        for (int i = 0; i < PB2; i++)
            FMA_PAIR(pbuf[i], RES2 + i);

        // 3) streamed k-pairs (L1): rolling ring, depth-3
        if (NGRP > 0) {
#pragma unroll 4
            for (int g = 0; g < NGRP; g++) {
                int slot = g & 3;
                int pb   = SB2 + g * 4;
#pragma unroll
                for (int i = 0; i < 4; i++)
                    FMA_PAIR(rbuf[slot][i], pb + i);
                int gp = g + 3;
                if (gp < NGRP) {
#pragma unroll
                    for (int i = 0; i < 4; i++)
                        rbuf[gp & 3][i] = *(const ull*)&WT[((SB2 + gp * 4 + i) * GSZ + j) * 2];
                }
            }
        }

        // ---- finalize gates: fold split-K + bias, write g_s[b][j] ----
        {
            ull acs[8] = {ac0, ac1, ac2, ac3, ac4, ac5, ac6, ac7};
#pragma unroll
            for (int b = 0; b < 8; b++) {
                float2 u = unp(acs[b]);
                g_s[b * GSZ + j] = u.x + u.y + bj;
            }
        }
        __syncthreads();
    }

    // ---- final update for t = T-1 ----
#pragma unroll
    for (int q = 0; q < 2; q++) {
        int m = um + 64 * q;
        float iv = sigm(g_s[ub * GSZ + m]);
        float fv = sigm(g_s[ub * GSZ + 128 + m]);
        float gv = tanh_f(g_s[ub * GSZ + 256 + m]);
        float ov = sigm(g_s[ub * GSZ + 384 + m]);
        float c  = fv * c_r[q] + iv * gv;
        float h  = ov * tanh_f(c);
        if (LAYER == 0)
            g_h1[(((size_t)(TLEN - 1)) * BATCH + b0 + ub) * HID + m] = h;
        else
            g_h2[(b0 + ub) * HID + m] = h;
    }
}

// ---------------- MLP head: relu(128->64) -> relu(64->32) -> 32->2 ----------------
__global__ void head_kernel(const float* __restrict__ W1, const float* __restrict__ b1,
                            const float* __restrict__ W2, const float* __restrict__ b2,
                            const float* __restrict__ W3, const float* __restrict__ b3,
                            float* __restrict__ out) {
    __shared__ float hrow[HID];
    __shared__ float z1[64];
    __shared__ float z2[32];
    int b   = blockIdx.x;
    int tid = threadIdx.x;  // 64 threads

    hrow[tid]      = g_h2[b * HID + tid];
    hrow[tid + 64] = g_h2[b * HID + tid + 64];
    __syncthreads();
    {
        float s = b1[tid];
        const float* w = &W1[tid * HID];
#pragma unroll 8
        for (int k = 0; k < HID; k++) s += w[k] * hrow[k];
        z1[tid] = fmaxf(s, 0.0f);
    }
    __syncthreads();
    if (tid < 32) {
        float s = b2[tid];
        const float* w = &W2[tid * 64];
#pragma unroll 8
        for (int k = 0; k < 64; k++) s += w[k] * z1[k];
        z2[tid] = fmaxf(s, 0.0f);
    }
    __syncthreads();
    if (tid < 2) {
        float s = b3[tid];
        const float* w = &W3[tid * 32];
#pragma unroll
        for (int k = 0; k < 32; k++) s += w[k] * z2[k];
        out[b * 2 + tid] = s;
    }
}

// ---------------- launch ----------------
extern "C" void kernel_launch(void* const* d_in, const int* in_sizes, int n_in,
                              void* d_out, int out_size) {
    const float* x    = (const float*)d_in[0];
    const float* Wih0 = (const float*)d_in[1];
    const float* Whh0 = (const float*)d_in[2];
    const float* bih0 = (const float*)d_in[3];
    const float* bhh0 = (const float*)d_in[4];
    const float* Wih1 = (const float*)d_in[5];
    const float* Whh1 = (const float*)d_in[6];
    const float* bih1 = (const float*)d_in[7];
    const float* bhh1 = (const float*)d_in[8];
    const float* W1   = (const float*)d_in[9];
    const float* b1   = (const float*)d_in[10];
    const float* W2   = (const float*)d_in[11];
    const float* b2   = (const float*)d_in[12];
    const float* W3   = (const float*)d_in[13];
    const float* b3   = (const float*)d_in[14];
    float* out = (float*)d_out;

    const int smem0 = (RES2 * GSZ * 2 + (KP0 / 2) * 20 + 8 * GSZ) * (int)sizeof(float); // 218,752 B
    const int smem1 = (RES2 * GSZ * 2 + (KP1 / 2) * 20 + 8 * GSZ) * (int)sizeof(float); // 223,232 B
    cudaFuncSetAttribute((const void*)lstm_kernel<0>,
                         cudaFuncAttributeMaxDynamicSharedMemorySize, smem0);
    cudaFuncSetAttribute((const void*)lstm_kernel<1>,
                         cudaFuncAttributeMaxDynamicSharedMemorySize, smem1);

    int tot = (KP0 + KP1) * GSZ + 2 * GSZ;
    prep_kernel<<<(tot + 255) / 256, 256>>>(Wih0, Whh0, bih0, bhh0,
                                            Wih1, Whh1, bih1, bhh1);
    lstm_kernel<0><<<NBLK, NTHR, smem0>>>(x);
    lstm_kernel<1><<<NBLK, NTHR, smem1>>>(nullptr);
    head_kernel<<<BATCH, 64>>>(W1, b1, W2, b2, W3, b3, out);
}

// round 8
// speedup vs baseline: 1.9625x; 1.4214x over previous
#include <cuda_runtime.h>
#include <cuda_bf16.h>
#include <cstdint>
#include <cstddef>

#define HID 128
#define GSZ 512
#define BATCH 1024
#define TLEN 512
#define DIN 12
#define KP0 144
#define KP1 128
#define SRR 96
#define BT 8
#define NBLK 128
#define MROWS (TLEN*BATCH)
#define AS 264

typedef unsigned long long ull;

__device__ float g_W0T[KP0*GSZ];
__device__ float g_W1T[KP1*GSZ];
__device__ float g_bias0[GSZ];
__device__ float g_bias1[GSZ];
__device__ __nv_bfloat16 g_h1s[(size_t)MROWS*256];   // [row][hi128|lo128]
__device__ __nv_bfloat16 g_BE[GSZ*384];              // [n][384] = wh|wh|wl
__device__ float g_xp1[(size_t)MROWS*GSZ];
__device__ float g_h2[BATCH*HID];

__device__ __forceinline__ ull dup2(float x){ull d;asm("mov.b64 %0,{%1,%1};":"=l"(d):"f"(x));return d;}
__device__ __forceinline__ ull pk2(float x,float y){ull d;asm("mov.b64 %0,{%1,%2};":"=l"(d):"f"(x),"f"(y));return d;}
__device__ __forceinline__ ull fma2(ull a,ull b,ull c){ull d;asm("fma.rn.f32x2 %0,%1,%2,%3;":"=l"(d):"l"(a),"l"(b),"l"(c));return d;}
__device__ __forceinline__ float2 unp(ull v){float2 r;asm("mov.b64 {%0,%1},%2;":"=f"(r.x),"=f"(r.y):"l"(v));return r;}
__device__ __forceinline__ float sigm(float x){return __fdividef(1.0f,1.0f+__expf(-x));}
__device__ __forceinline__ float tanh_f(float x){return __fdividef(2.0f,1.0f+__expf(-2.0f*x))-1.0f;}

#define FMA_ROW(W2V,KIDX) do{ \
    ull w0=dup2((W2V).x), w1=dup2((W2V).y); \
    ulonglong2 vA=*(const ulonglong2*)&v_s[(KIDX)*12]; \
    ulonglong2 vB=*(const ulonglong2*)&v_s[(KIDX)*12+4]; \
    a0=fma2(w0,vA.x,a0); a1=fma2(w0,vA.y,a1); \
    a2=fma2(w0,vB.x,a2); a3=fma2(w0,vB.y,a3); \
    a4=fma2(w1,vA.x,a4); a5=fma2(w1,vA.y,a5); \
    a6=fma2(w1,vB.x,a6); a7=fma2(w1,vB.y,a7); }while(0)

#define MMA(d,a,b0,b1) \
    asm volatile("mma.sync.aligned.m16n8k16.row.col.f32.bf16.bf16.f32 " \
        "{%0,%1,%2,%3},{%4,%5,%6,%7},{%8,%9},{%0,%1,%2,%3};" \
        : "+f"((d)[0]),"+f"((d)[1]),"+f"((d)[2]),"+f"((d)[3]) \
        : "r"((a)[0]),"r"((a)[1]),"r"((a)[2]),"r"((a)[3]),"r"(b0),"r"(b1))

__global__ void prep_kernel(const float* __restrict__ Wih0,const float* __restrict__ Whh0,
                            const float* __restrict__ bih0,const float* __restrict__ bhh0,
                            const float* __restrict__ Wih1,const float* __restrict__ Whh1,
                            const float* __restrict__ bih1,const float* __restrict__ bhh1){
    int i = blockIdx.x*blockDim.x + threadIdx.x;
    const int S0=KP0*GSZ, S1=S0+KP1*GSZ, S2=S1+GSZ, S3=S2+GSZ, S4=S3+GSZ*384;
    if(i<S0){
        int k=i/GSZ, j=i%GSZ; float v=0.f;
        if(k<DIN) v=Wih0[j*DIN+k]; else if(k<DIN+HID) v=Whh0[j*HID+(k-DIN)];
        g_W0T[i]=v;
    }else if(i<S1){
        int i2=i-S0; int k=i2/GSZ, j=i2%GSZ;
        g_W1T[i2]=Whh1[j*HID+k];
    }else if(i<S2){ int j=i-S1; g_bias0[j]=bih0[j]+bhh0[j]; }
    else if(i<S3){ int j=i-S2; g_bias1[j]=bih1[j]+bhh1[j]; }
    else if(i<S4){
        int i2=i-S3; int n=i2/384, kp=i2%384, k=kp&127;
        float w=Wih1[n*HID+k];
        __nv_bfloat16 hi=__float2bfloat16(w);
        g_BE[i2] = (kp<256)? hi : __float2bfloat16(w-__bfloat162float(hi));
    }
}

// xp1 = h1(split bf16) @ W_ih1^T + b1, via mma.sync, unified K_ext=384.
__global__ void __launch_bounds__(256,1) xp_gemm_kernel(){
    extern __shared__ __nv_bfloat16 As[];     // [128][AS]
    int tid=threadIdx.x, wid=tid>>5, lane=tid&31;
    int g=lane>>2, t=lane&3;
    size_t mbase=(size_t)blockIdx.x*128;
    {
        const float4* src=(const float4*)(g_h1s + mbase*256);
        for(int i=tid;i<4096;i+=256){
            int r=i>>5, c=i&31;
            *(float4*)(As + r*AS + c*8)=src[r*32+c];
        }
    }
    __syncthreads();
    int n0=blockIdx.y*128 + (wid>>2)*64;
    int m0=(wid&3)*32;
    float acc[2][8][4];
#pragma unroll
    for(int mi=0;mi<2;mi++)
#pragma unroll
        for(int ni=0;ni<8;ni++)
#pragma unroll
            for(int q=0;q<4;q++) acc[mi][ni][q]=0.f;
#pragma unroll 1
    for(int kc=0;kc<24;kc++){
        int ks=(kc<8)?kc*16:(kc<16)?(128+(kc-8)*16):((kc-16)*16);
        int kb=kc*16;
        uint32_t a[2][4];
#pragma unroll
        for(int mi=0;mi<2;mi++){
            const __nv_bfloat16* ap=As+(m0+mi*16)*AS+ks;
            a[mi][0]=*(const uint32_t*)(ap+g*AS+2*t);
            a[mi][1]=*(const uint32_t*)(ap+(g+8)*AS+2*t);
            a[mi][2]=*(const uint32_t*)(ap+g*AS+2*t+8);
            a[mi][3]=*(const uint32_t*)(ap+(g+8)*AS+2*t+8);
        }
#pragma unroll
        for(int ni=0;ni<8;ni++){
            const __nv_bfloat16* bp=g_BE+(size_t)(n0+ni*8+g)*384+kb;
            uint32_t b0=*(const uint32_t*)(bp+2*t);
            uint32_t b1=*(const uint32_t*)(bp+2*t+8);
            MMA(acc[0][ni],a[0],b0,b1);
            MMA(acc[1][ni],a[1],b0,b1);
        }
    }
#pragma unroll
    for(int mi=0;mi<2;mi++)
#pragma unroll
        for(int ni=0;ni<8;ni++){
            int col=n0+ni*8+2*t;
            float bx=g_bias1[col], by=g_bias1[col+1];
            size_t r0=mbase+m0+mi*16+g;
            *(float2*)&g_xp1[r0*GSZ+col]     = make_float2(acc[mi][ni][0]+bx, acc[mi][ni][1]+by);
            *(float2*)&g_xp1[(r0+8)*GSZ+col] = make_float2(acc[mi][ni][2]+bx, acc[mi][ni][3]+by);
        }
}

// fused LSTM scan (R4 skeleton, fully weight-resident)
template <int LAYER>
__global__ void __launch_bounds__(256,1) lstm_kernel(const float* __restrict__ x){
    constexpr int KP=(LAYER==0)?KP0:KP1;
    constexpr int PRM=KP-SRR;                 // 48 / 32
    constexpr int KOFF=(LAYER==0)?DIN:0;
    const float* __restrict__ WT=(LAYER==0)?g_W0T:g_W1T;

    extern __shared__ float smem[];
    float* w_s=smem;                 // SRR*512
    float* v_s=w_s+SRR*GSZ;          // KP*12
    float* g_s=v_s+KP*12;            // 8*512

    const int tid=threadIdx.x;
    const int b0=blockIdx.x*BT;
    const int j0=2*tid;
    {
        const float2* src=(const float2*)WT;
        float2* dst=(float2*)w_s;
        for(int i=tid;i<SRR*GSZ/2;i+=256) dst[i]=src[i];
    }
    for(int i=tid;i<KP*12;i+=256) v_s[i]=0.f;

    float2 pbuf[PRM];
#pragma unroll
    for(int i=0;i<PRM;i++) pbuf[i]=*(const float2*)&WT[(SRR+i)*GSZ+j0];

    ull bxd=0, byd=0;
    if(LAYER==0){
        float2 bj=*(const float2*)&g_bias0[j0];
        bxd=dup2(bj.x); byd=dup2(bj.y);
    }
    const int ub=tid>>5, um=tid&31;
    float c_r[4]={0.f,0.f,0.f,0.f};

    for(int t=0;t<TLEN;t++){
        float xstage=0.f; float2 xpr[8];
        int st_r=0, st_d=0;
        if(LAYER==0){
            if(tid<96){ st_r=tid/12; st_d=tid%12;
                xstage=x[(((size_t)(b0+st_r))*TLEN+t)*DIN+st_d]; }
        }else{
            const float* xpb=g_xp1+(((size_t)t)*BATCH+b0)*GSZ+j0;
#pragma unroll
            for(int b=0;b<8;b++) xpr[b]=*(const float2*)(xpb+(size_t)b*GSZ);
        }
        if(t>0){
#pragma unroll
            for(int q=0;q<4;q++){
                int m=um+32*q;
                float iv=sigm(g_s[ub*GSZ+m]);
                float fv=sigm(g_s[ub*GSZ+128+m]);
                float gv=tanh_f(g_s[ub*GSZ+256+m]);
                float ov=sigm(g_s[ub*GSZ+384+m]);
                float c=fv*c_r[q]+iv*gv; c_r[q]=c;
                float h=ov*tanh_f(c);
                v_s[(KOFF+m)*12+ub]=h;
                if(LAYER==0){
                    size_t row=((size_t)(t-1))*BATCH+b0+ub;
                    __nv_bfloat16 hb=__float2bfloat16(h);
                    g_h1s[row*256+m]=hb;
                    g_h1s[row*256+128+m]=__float2bfloat16(h-__bfloat162float(hb));
                }
            }
        }
        if(LAYER==0){ if(tid<96) v_s[st_d*12+st_r]=xstage; }
        __syncthreads();

        ull a0,a1,a2,a3,a4,a5,a6,a7;
        if(LAYER==0){ a0=bxd;a1=bxd;a2=bxd;a3=bxd; a4=byd;a5=byd;a6=byd;a7=byd; }
        else{
            a0=pk2(xpr[0].x,xpr[1].x); a1=pk2(xpr[2].x,xpr[3].x);
            a2=pk2(xpr[4].x,xpr[5].x); a3=pk2(xpr[6].x,xpr[7].x);
            a4=pk2(xpr[0].y,xpr[1].y); a5=pk2(xpr[2].y,xpr[3].y);
            a6=pk2(xpr[4].y,xpr[5].y); a7=pk2(xpr[6].y,xpr[7].y);
        }
#pragma unroll 4
        for(int k=0;k<SRR;k++){
            float2 w=*(const float2*)&w_s[k*GSZ+j0];
            FMA_ROW(w,k);
        }
#pragma unroll
        for(int i=0;i<PRM;i++) FMA_ROW(pbuf[i],SRR+i);
        {
            ull ac0[4]={a0,a1,a2,a3}, ac1[4]={a4,a5,a6,a7};
#pragma unroll
            for(int p=0;p<4;p++){
                float2 u0=unp(ac0[p]), u1=unp(ac1[p]);
                *(float2*)&g_s[(2*p)*GSZ+j0]  =make_float2(u0.x,u1.x);
                *(float2*)&g_s[(2*p+1)*GSZ+j0]=make_float2(u0.y,u1.y);
            }
        }
        __syncthreads();
    }
#pragma unroll
    for(int q=0;q<4;q++){
        int m=um+32*q;
        float iv=sigm(g_s[ub*GSZ+m]);
        float fv=sigm(g_s[ub*GSZ+128+m]);
        float gv=tanh_f(g_s[ub*GSZ+256+m]);
        float ov=sigm(g_s[ub*GSZ+384+m]);
        float c=fv*c_r[q]+iv*gv;
        float h=ov*tanh_f(c);
        if(LAYER==0){
            size_t row=((size_t)(TLEN-1))*BATCH+b0+ub;
            __nv_bfloat16 hb=__float2bfloat16(h);
            g_h1s[row*256+m]=hb;
            g_h1s[row*256+128+m]=__float2bfloat16(h-__bfloat162float(hb));
        }else g_h2[(b0+ub)*HID+m]=h;
    }
}

__global__ void head_kernel(const float* __restrict__ W1,const float* __restrict__ b1,
                            const float* __restrict__ W2,const float* __restrict__ b2,
                            const float* __restrict__ W3,const float* __restrict__ b3,
                            float* __restrict__ out){
    __shared__ float hrow[HID]; __shared__ float z1[64]; __shared__ float z2[32];
    int b=blockIdx.x, tid=threadIdx.x;
    hrow[tid]=g_h2[b*HID+tid];
    hrow[tid+64]=g_h2[b*HID+tid+64];
    __syncthreads();
    {
        float s=b1[tid];
        const float* w=&W1[tid*HID];
#pragma unroll 8
        for(int k=0;k<HID;k++) s+=w[k]*hrow[k];
        z1[tid]=fmaxf(s,0.f);
    }
    __syncthreads();
    if(tid<32){
        float s=b2[tid];
        const float* w=&W2[tid*64];
#pragma unroll 8
        for(int k=0;k<64;k++) s+=w[k]*z1[k];
        z2[tid]=fmaxf(s,0.f);
    }
    __syncthreads();
    if(tid<2){
        float s=b3[tid];
        const float* w=&W3[tid*32];
#pragma unroll
        for(int k=0;k<32;k++) s+=w[k]*z2[k];
        out[b*2+tid]=s;
    }
}

extern "C" void kernel_launch(void* const* d_in, const int* in_sizes, int n_in,
                              void* d_out, int out_size){
    const float* x   =(const float*)d_in[0];
    const float* Wih0=(const float*)d_in[1];
    const float* Whh0=(const float*)d_in[2];
    const float* bih0=(const float*)d_in[3];
    const float* bhh0=(const float*)d_in[4];
    const float* Wih1=(const float*)d_in[5];
    const float* Whh1=(const float*)d_in[6];
    const float* bih1=(const float*)d_in[7];
    const float* bhh1=(const float*)d_in[8];
    const float* W1=(const float*)d_in[9];
    const float* b1=(const float*)d_in[10];
    const float* W2=(const float*)d_in[11];
    const float* b2=(const float*)d_in[12];
    const float* W3=(const float*)d_in[13];
    const float* b3=(const float*)d_in[14];
    float* out=(float*)d_out;

    const int smem0=(SRR*GSZ+KP0*12+8*GSZ)*4;    // 219,904 B
    const int smem1=(SRR*GSZ+KP1*12+8*GSZ)*4;    // 219,136 B
    const int smemg=128*AS*2;                     // 67,584 B
    cudaFuncSetAttribute((const void*)lstm_kernel<0>,cudaFuncAttributeMaxDynamicSharedMemorySize,smem0);
    cudaFuncSetAttribute((const void*)lstm_kernel<1>,cudaFuncAttributeMaxDynamicSharedMemorySize,smem1);
    cudaFuncSetAttribute((const void*)xp_gemm_kernel,cudaFuncAttributeMaxDynamicSharedMemorySize,smemg);

    int tot=(KP0+KP1)*GSZ+2*GSZ+GSZ*384;
    prep_kernel<<<(tot+255)/256,256>>>(Wih0,Whh0,bih0,bhh0,Wih1,Whh1,bih1,bhh1);
    lstm_kernel<0><<<NBLK,256,smem0>>>(x);
    xp_gemm_kernel<<<dim3(MROWS/128,4),256,smemg>>>();
    lstm_kernel<1><<<NBLK,256,smem1>>>(nullptr);
    head_kernel<<<BATCH,64>>>(W1,b1,W2,b2,W3,b3,out);
}